// round 2
// baseline (speedup 1.0000x reference)
#include <cuda_runtime.h>
#include <cstdint>

// out[b, bin, d] = ce[chr[b]-1, d]
// BS=512, BINS=2001, DIM=128, N_CHR=24
// Pure store-bandwidth kernel: 512*2001*128*4B = 524.5 MB written.

static constexpr int BS = 512;
static constexpr int BINS = 2001;
static constexpr int DIM = 128;            // 32 float4 per row
static constexpr int THREADS = 256;        // 8 bins per iteration
static constexpr int CHUNKS = 16;          // bin-chunks per sample
static constexpr int BINS_PER_CHUNK = (BINS + CHUNKS - 1) / CHUNKS;  // 126

__global__ __launch_bounds__(THREADS)
void chrom_embed_kernel(const int* __restrict__ chr,
                        const float4* __restrict__ ce4,   // [24, 32] float4
                        float4* __restrict__ out4)        // [512, 2001, 32] float4
{
    const int b     = blockIdx.y;
    const int chunk = blockIdx.x;

    const int row = chr[b] - 1;                 // 0..23
    const int col = threadIdx.x & 31;           // float4 column within the row
    const int binOfs = threadIdx.x >> 5;        // 0..7

    // Broadcast load of this sample's embedding row chunk (one float4/thread).
    const float4 v = ce4[row * (DIM / 4) + col];

    const int binStart = chunk * BINS_PER_CHUNK;
    int binEnd = binStart + BINS_PER_CHUNK;
    if (binEnd > BINS) binEnd = BINS;

    // Base pointer for this sample.
    float4* __restrict__ dst = out4 + (size_t)b * BINS * (DIM / 4) + col;

    for (int bin = binStart + binOfs; bin < binEnd; bin += THREADS / 32) {
        dst[(size_t)bin * (DIM / 4)] = v;
    }
}

extern "C" void kernel_launch(void* const* d_in, const int* in_sizes, int n_in,
                              void* d_out, int out_size)
{
    // Inputs per reference order: tensor [512,2001] f32 (unused),
    // chr [512] int32, ce [24,128] f32.
    const int*    chr = (const int*)d_in[1];
    const float4* ce4 = (const float4*)d_in[2];
    float4*       out = (float4*)d_out;

    dim3 grid(CHUNKS, BS);
    chrom_embed_kernel<<<grid, THREADS>>>(chr, ce4, out);
}

// round 4
// speedup vs baseline: 1.0009x; 1.0009x over previous
#include <cuda_runtime.h>
#include <cstdint>

// out[b, bin, d] = ce[chr[b]-1, d]
// BS=512, BINS=2001, DIM=128, N_CHR=24
// Pure store-bandwidth kernel: 512*2001*128*4B = 524.5 MB written.
// R2/R3: streaming stores (st.global.cs, evict-first) + 2x unrolled bin loop.
// (R3 = identical resubmit of R2; round 3 bench was an infra failure.)

static constexpr int BS = 512;
static constexpr int BINS = 2001;
static constexpr int DIM = 128;            // 32 float4 per row
static constexpr int THREADS = 256;        // 8 bins per iteration
static constexpr int CHUNKS = 16;          // bin-chunks per sample
static constexpr int BINS_PER_CHUNK = (BINS + CHUNKS - 1) / CHUNKS;  // 126

__device__ __forceinline__ void stcs4(float4* p, const float4& v) {
    asm volatile("st.global.cs.v4.f32 [%0], {%1, %2, %3, %4};"
                 :: "l"(p), "f"(v.x), "f"(v.y), "f"(v.z), "f"(v.w)
                 : "memory");
}

__global__ __launch_bounds__(THREADS)
void chrom_embed_kernel(const int* __restrict__ chr,
                        const float4* __restrict__ ce4,   // [24, 32] float4
                        float4* __restrict__ out4)        // [512, 2001, 32] float4
{
    const int b     = blockIdx.y;
    const int chunk = blockIdx.x;

    const int row = chr[b] - 1;                 // 0..23
    const int col = threadIdx.x & 31;           // float4 column within the row
    const int binOfs = threadIdx.x >> 5;        // 0..7 (warp id)

    // Broadcast load of this sample's embedding row (one float4/thread).
    const float4 v = ce4[row * (DIM / 4) + col];

    const int binStart = chunk * BINS_PER_CHUNK;
    int binEnd = binStart + BINS_PER_CHUNK;
    if (binEnd > BINS) binEnd = BINS;

    float4* __restrict__ dst = out4 + (size_t)b * BINS * (DIM / 4) + col;

    constexpr int STEP = THREADS / 32;   // 8 bins per iteration
    int bin = binStart + binOfs;

    // 2x unrolled: two independent streaming stores in flight per warp slot.
    for (; bin + STEP < binEnd; bin += 2 * STEP) {
        stcs4(dst + (size_t)bin * (DIM / 4), v);
        stcs4(dst + (size_t)(bin + STEP) * (DIM / 4), v);
    }
    if (bin < binEnd) {
        stcs4(dst + (size_t)bin * (DIM / 4), v);
    }
}

extern "C" void kernel_launch(void* const* d_in, const int* in_sizes, int n_in,
                              void* d_out, int out_size)
{
    // Inputs per reference order: tensor [512,2001] f32 (unused),
    // chr [512] int32, ce [24,128] f32.
    const int*    chr = (const int*)d_in[1];
    const float4* ce4 = (const float4*)d_in[2];
    float4*       out = (float4*)d_out;

    dim3 grid(CHUNKS, BS);
    chrom_embed_kernel<<<grid, THREADS>>>(chr, ce4, out);
}